// round 1
// baseline (speedup 1.0000x reference)
#include <cuda_runtime.h>
#include <math.h>

#define NPFS  4
#define NF    512
#define NP    256
#define BATCH 128
#define NMAT  (BATCH * NPFS)            // 512 matrices
#define TRI_ELEMS ((NP * (NP - 1)) / 2) // 32640

// Scratch (allocations are forbidden; __device__ globals are the sanctioned path)
__device__ float g_Ffull[NPFS * NF * NF];   // antisymmetrized F, 4 MB (L2-resident)
__device__ float g_sign[NMAT];
__device__ float g_logabs[NMAT];

__device__ __forceinline__ unsigned tri(int r) {
    return ((unsigned)(r * (r - 1))) >> 1;   // base of row r in lower triangle
}

// ---------------------------------------------------------------------------
// Kernel 1: F_full = 0.5 * (F - F^T) for each of the 4 pfaffian matrices
// ---------------------------------------------------------------------------
__global__ void prep_kernel(const float* __restrict__ F) {
    int i = blockIdx.x * 256 + threadIdx.x;         // 0 .. 4*512*512-1
    int p   = i >> 18;
    int rem = i & ((1 << 18) - 1);
    int r = rem >> 9;
    int c = rem & (NF - 1);
    float a = F[i];
    float b = F[(p << 18) + (c << 9) + r];
    g_Ffull[i] = 0.5f * (a - b);
}

// ---------------------------------------------------------------------------
// Kernel 2: one CTA per (batch, pf) matrix. Lower triangle of the skew matrix
// lives in dynamic smem. Parlett-Reid elimination with partial pivoting.
// ---------------------------------------------------------------------------
__global__ __launch_bounds__(256, 1)
void pf_kernel(const int* __restrict__ idx) {
    extern __shared__ float sm[];
    float* L   = sm;                 // [TRI_ELEMS]  L[tri(r)+c] = A[r][c], r>c
    float* tau = sm + TRI_ELEMS;     // [NP]
    float* v   = tau + NP;           // [NP]

    __shared__ int   s_idx[NP];
    __shared__ float s_rv[8];
    __shared__ int   s_ri[8];

    const int tid  = threadIdx.x;
    const int lane = tid & 31;
    const int wid  = tid >> 5;
    const int m    = blockIdx.x;     // matrix id
    const int b    = m >> 2;
    const int p    = m & 3;

    s_idx[tid] = idx[b * NP + tid];
    __syncthreads();

    // ---- gather: L[r][c] = Ffull[p][idx[r]][idx[c]], r > c (warp per row) ----
    {
        const float* Fp = g_Ffull + (size_t)p * (NF * NF);
        for (int r = wid; r < NP; r += 8) {
            const float* row = Fp + (size_t)s_idx[r] * NF;
            unsigned base = tri(r);
            for (int c = lane; c < r; c += 32)
                L[base + c] = __ldg(&row[s_idx[c]]);
        }
    }
    __syncthreads();

    float sign = 1.f, logabs = 0.f;   // live in thread 0

    for (int k = 0; k < NP; k += 2) {
        const int p1 = k + 1;

        // ---- pivot search: argmax_{r>k} |A[r][k]|, lowest index on ties ----
        float bv = -1.f; int bi = NP;
        {
            int r = tid;
            if (r > k) { bv = fabsf(L[tri(r) + k]); bi = r; }
            #pragma unroll
            for (int off = 16; off; off >>= 1) {
                float ov = __shfl_down_sync(0xffffffffu, bv, off);
                int   oi = __shfl_down_sync(0xffffffffu, bi, off);
                if (ov > bv || (ov == bv && oi < bi)) { bv = ov; bi = oi; }
            }
            if (lane == 0) { s_rv[wid] = bv; s_ri[wid] = bi; }
        }
        __syncthreads();
        bv = s_rv[0]; bi = s_ri[0];
        #pragma unroll
        for (int w = 1; w < 8; w++) {
            float ov = s_rv[w]; int oi = s_ri[w];
            if (ov > bv || (ov == bv && oi < bi)) { bv = ov; bi = oi; }
        }
        const int kp = bi;   // pivot row, kp in (k, 255]

        // ---- symmetric swap of indices p1 <-> kp on the lower triangle ----
        if (kp != p1) {
            const int t = tid;
            const unsigned tp1 = tri(p1), tq = tri(kp);
            if (t < p1) {
                float a = L[tp1 + t], c2 = L[tq + t];
                L[tp1 + t] = c2;  L[tq + t] = a;
            } else if (t == p1) {
                L[tq + p1] = -L[tq + p1];
            } else if (t < kp) {
                const unsigned tt = tri(t);
                float a = L[tt + p1], c2 = L[tq + t];
                L[tt + p1] = -c2;  L[tq + t] = -a;
            } else if (t > kp) {
                const unsigned tt = tri(t);
                float a = L[tt + p1], c2 = L[tt + kp];
                L[tt + p1] = c2;  L[tt + kp] = a;
            }
        }
        __syncthreads();

        // ---- pivot value, sign/log accumulation, tau & v fill ----
        const float piv = -L[tri(p1) + k];          // A[k][k+1] (broadcast LDS)
        if (tid == 0) {
            if (kp != p1) sign = -sign;
            if (piv < 0.f) sign = -sign;
            logabs += logf(fabsf(piv));
        }
        {
            int r = tid;
            if (r >= k + 2) {
                tau[r] = L[tri(r) + k] / piv;       // A[r][k]/piv
                v[r]   = L[tri(r) + p1];            // A[r][k+1]
            }
        }
        __syncthreads();

        // ---- rank-2 update on trailing triangle: A[r][c] += v_r*tau_c - tau_r*v_c
        if (k + 2 < NP) {
            for (int r = k + 2 + wid; r < NP; r += 8) {
                const unsigned base = tri(r);
                const float tr = tau[r], vr = v[r];
                #pragma unroll 4
                for (int c = k + 2 + lane; c < r; c += 32) {
                    float x = L[base + c];
                    L[base + c] = x + vr * tau[c] - tr * v[c];
                }
            }
        }
        __syncthreads();
    }

    if (tid == 0) { g_sign[m] = sign; g_logabs[m] = logabs; }
}

// ---------------------------------------------------------------------------
// Kernel 3: signed logsumexp over the 4 pfaffians per batch element
// ---------------------------------------------------------------------------
__global__ void combine_kernel(float* __restrict__ out) {
    int b = threadIdx.x;
    if (b < BATCH) {
        float la[NPFS], sg[NPFS];
        float mx = -INFINITY;
        #pragma unroll
        for (int p = 0; p < NPFS; p++) {
            la[p] = g_logabs[b * NPFS + p];
            sg[p] = g_sign[b * NPFS + p];
            mx = fmaxf(mx, la[p]);
        }
        float val = 0.f;
        #pragma unroll
        for (int p = 0; p < NPFS; p++)
            val += sg[p] * expf(la[p] - mx);
        out[b]         = (val > 0.f) ? 1.f : ((val < 0.f) ? -1.f : 0.f);
        out[BATCH + b] = mx + logf(fabsf(val));
    }
}

// ---------------------------------------------------------------------------
extern "C" void kernel_launch(void* const* d_in, const int* in_sizes, int n_in,
                              void* d_out, int out_size) {
    const float* F   = (const float*)d_in[0];   // (4, 512, 512) fp32
    const int*   idx = (const int*)  d_in[1];   // (128, 256) int32
    float*       out = (float*)d_out;           // (2, 128) fp32

    const size_t shmem = (size_t)(TRI_ELEMS + 2 * NP) * sizeof(float); // ~132.6 KB
    cudaFuncSetAttribute(pf_kernel, cudaFuncAttributeMaxDynamicSharedMemorySize,
                         (int)shmem);

    prep_kernel<<<(NPFS * NF * NF) / 256, 256>>>(F);
    pf_kernel<<<NMAT, 256, shmem>>>(idx);
    combine_kernel<<<1, 128>>>(out);
}